// round 9
// baseline (speedup 1.0000x reference)
#include <cuda_runtime.h>
#include <cuda_bf16.h>
#include <cstddef>
#include <cstdint>

#define BB   4
#define SS   1024
#define DD   1024
#define HH   16
#define HDD  64
#define MM   (BB * SS)
#define BHT  (BB * HH)
#define OUT_ELEMS    ((size_t)BB * SS * DD)
#define W_ELEMS      ((size_t)BB * HH * SS * SS)

typedef __nv_bfloat16 bf16;

__device__ float g_wscratch[W_ELEMS];
__device__ float g_rowinv[BHT * SS];
__device__ bf16 g_Qhi[BHT * SS * HDD];
__device__ bf16 g_Qlo[BHT * SS * HDD];
__device__ bf16 g_Khi[BHT * SS * HDD];
__device__ bf16 g_Klo[BHT * SS * HDD];
__device__ bf16 g_Vhi[BHT * SS * HDD];
__device__ bf16 g_Vlo[BHT * SS * HDD];
__device__ bf16 g_inhi[3][MM * DD];
__device__ bf16 g_inlo[3][MM * DD];
__device__ bf16 g_WThi[4][DD * DD];
__device__ bf16 g_WTlo[4][DD * DD];
__device__ bf16 g_ctxhi[MM * DD];
__device__ bf16 g_ctxlo[MM * DD];

__device__ __forceinline__ uint32_t smem_u32(const void* p) {
    uint32_t a;
    asm("{ .reg .u64 t; cvta.to.shared.u64 t, %1; cvt.u32.u64 %0, t; }"
        : "=r"(a) : "l"(p));
    return a;
}

#define LDSM4(r0, r1, r2, r3, a)                                            \
    asm volatile("ldmatrix.sync.aligned.m8n8.x4.shared.b16 {%0,%1,%2,%3}, [%4];" \
        : "=r"(r0), "=r"(r1), "=r"(r2), "=r"(r3) : "r"(a))
#define LDSM4T(r0, r1, r2, r3, a)                                           \
    asm volatile("ldmatrix.sync.aligned.m8n8.x4.trans.shared.b16 {%0,%1,%2,%3}, [%4];" \
        : "=r"(r0), "=r"(r1), "=r"(r2), "=r"(r3) : "r"(a))
#define MMA16816(c, a0, a1, a2, a3, b0, b1)                                 \
    asm volatile("mma.sync.aligned.m16n8k16.row.col.f32.bf16.bf16.f32 "     \
        "{%0,%1,%2,%3}, {%4,%5,%6,%7}, {%8,%9}, {%0,%1,%2,%3};"             \
        : "+f"((c)[0]), "+f"((c)[1]), "+f"((c)[2]), "+f"((c)[3])            \
        : "r"(a0), "r"(a1), "r"(a2), "r"(a3), "r"(b0), "r"(b1))
#define CP16(smaddr, gptr)                                                  \
    asm volatile("cp.async.cg.shared.global [%0], [%1], 16;"                \
        :: "r"(smaddr), "l"(gptr))
#define CP_COMMIT() asm volatile("cp.async.commit_group;" ::: "memory")
#define CP_WAIT1()  asm volatile("cp.async.wait_group 1;"  ::: "memory")

__device__ __forceinline__ void split4(float4 v, uint2& hi, uint2& lo) {
    __nv_bfloat162 h0 = __float22bfloat162_rn(make_float2(v.x, v.y));
    __nv_bfloat162 h1 = __float22bfloat162_rn(make_float2(v.z, v.w));
    float2 f0 = __bfloat1622float2(h0);
    float2 f1 = __bfloat1622float2(h1);
    __nv_bfloat162 l0 = __float22bfloat162_rn(make_float2(v.x - f0.x, v.y - f0.y));
    __nv_bfloat162 l1 = __float22bfloat162_rn(make_float2(v.z - f1.x, v.w - f1.y));
    hi.x = *(uint32_t*)&h0; hi.y = *(uint32_t*)&h1;
    lo.x = *(uint32_t*)&l0; lo.y = *(uint32_t*)&l1;
}

// ===================== input split: fp32 -> bf16 hi/lo =====================
__global__ __launch_bounds__(256) void split_kernel(
    const float* __restrict__ src, bf16* __restrict__ hi, bf16* __restrict__ lo)
{
    const size_t base = ((size_t)blockIdx.x * 256 + threadIdx.x) * 8;
    float4 a = *(const float4*)&src[base];
    float4 b = *(const float4*)&src[base + 4];
    uint2 h0, l0, h1, l1;
    split4(a, h0, l0);
    split4(b, h1, l1);
    uint4 hv; hv.x = h0.x; hv.y = h0.y; hv.z = h1.x; hv.w = h1.y;
    uint4 lv; lv.x = l0.x; lv.y = l0.y; lv.z = l1.x; lv.w = l1.y;
    *(uint4*)&hi[base] = hv;
    *(uint4*)&lo[base] = lv;
}

// ===================== weight transpose + split ============================
__global__ __launch_bounds__(256) void transpose_split_kernel(
    const float* __restrict__ src, bf16* __restrict__ dhi, bf16* __restrict__ dlo)
{
    __shared__ float t[32][33];
    const int tid = threadIdx.x;
    const int x = blockIdx.x * 32 + (tid & 31);
    const int y0 = blockIdx.y * 32 + (tid >> 5);
#pragma unroll
    for (int r = 0; r < 4; r++)
        t[(tid >> 5) + r * 8][tid & 31] = src[(size_t)(y0 + r * 8) * DD + x];
    __syncthreads();
    const int x2 = blockIdx.y * 32 + (tid & 31);
    const int y2 = blockIdx.x * 32 + (tid >> 5);
#pragma unroll
    for (int r = 0; r < 4; r++) {
        const float v = t[tid & 31][(tid >> 5) + r * 8];
        const bf16 h = __float2bfloat16(v);
        const bf16 l = __float2bfloat16(v - __bfloat162float(h));
        dhi[(size_t)(y2 + r * 8) * DD + x2] = h;
        dlo[(size_t)(y2 + r * 8) * DD + x2] = l;
    }
}

// ===================== bf16x3 GEMM, 128x256 tile, cp.async =================
#define GA_HI 0
#define GA_LO 10240
#define GB_HI 20480
#define GB_LO 40960
#define STAGE_B 61440
#define GEMM_SMEM3 (3 * STAGE_B)

template <int MODE>
__global__ __launch_bounds__(512, 1) void gemm_bf16_kernel(
    const bf16* __restrict__ Ahi, const bf16* __restrict__ Alo,
    const bf16* __restrict__ Bhi, const bf16* __restrict__ Blo,
    const float* __restrict__ bias, float* __restrict__ C,
    bf16* __restrict__ Chi, bf16* __restrict__ Clo)
{
    extern __shared__ char smem[];
    const uint32_t sb = smem_u32(smem);
    const int tid  = threadIdx.x;
    const int wid  = tid >> 5;
    const int lane = tid & 31;
    const int wm   = wid & 1;
    const int wn   = wid >> 1;
    const int m0 = blockIdx.y * 128;
    const int n0 = blockIdx.x * 256;

    float acc[4][4][4];
#pragma unroll
    for (int i = 0; i < 4; i++)
#pragma unroll
        for (int j = 0; j < 4; j++)
#pragma unroll
            for (int q = 0; q < 4; q++) acc[i][j][q] = 0.f;

    auto issue = [&](int c) {
        if (c < 32) {
            const uint32_t st = sb + (c % 3) * STAGE_B;
            const int k0 = c * 32;
            {
                const int row = tid >> 2, g = tid & 3;
                const size_t ga = (size_t)(m0 + row) * DD + k0 + g * 8;
                const uint32_t so = (uint32_t)(row * 80 + g * 16);
                CP16(st + GA_HI + so, Ahi + ga);
                CP16(st + GA_LO + so, Alo + ga);
            }
#pragma unroll
            for (int r = 0; r < 2; r++) {
                const int idx = tid + r * 512;
                const int row = idx >> 2, g = idx & 3;
                const size_t gb = (size_t)(n0 + row) * DD + k0 + g * 8;
                const uint32_t so = (uint32_t)(row * 80 + g * 16);
                CP16(st + GB_HI + so, Bhi + gb);
                CP16(st + GB_LO + so, Blo + gb);
            }
        }
        CP_COMMIT();
    };

    issue(0);
    issue(1);

    const uint32_t a_off = (uint32_t)((wm * 64 + (lane & 15)) * 80 + (lane >> 4) * 16);
    const uint32_t b_off = (uint32_t)((wn * 32 + (lane & 15)) * 80 + (lane >> 4) * 16);

    for (int c = 0; c < 32; c++) {
        CP_WAIT1();
        __syncthreads();
        issue(c + 2);

        const uint32_t bb = sb + (c % 3) * STAGE_B;
#pragma unroll
        for (int ks = 0; ks < 2; ks++) {
            uint32_t ah[4][4], al[4][4], bh[2][4], bl[2][4];
#pragma unroll
            for (int mt = 0; mt < 4; mt++) {
                const uint32_t ad = bb + a_off + (uint32_t)(mt * 16 * 80 + ks * 32);
                LDSM4(ah[mt][0], ah[mt][1], ah[mt][2], ah[mt][3], ad + GA_HI);
                LDSM4(al[mt][0], al[mt][1], al[mt][2], al[mt][3], ad + GA_LO);
            }
#pragma unroll
            for (int p = 0; p < 2; p++) {
                const uint32_t bd = bb + b_off + (uint32_t)(p * 16 * 80 + ks * 32);
                LDSM4(bh[p][0], bh[p][1], bh[p][2], bh[p][3], bd + GB_HI);
                LDSM4(bl[p][0], bl[p][1], bl[p][2], bl[p][3], bd + GB_LO);
            }
#pragma unroll
            for (int mt = 0; mt < 4; mt++) {
#pragma unroll
                for (int nt = 0; nt < 4; nt++) {
                    const int p = nt >> 1, q2 = nt & 1;
                    MMA16816(acc[mt][nt], ah[mt][0], ah[mt][1], ah[mt][2], ah[mt][3],
                             bh[p][q2], bh[p][q2 + 2]);
                    MMA16816(acc[mt][nt], ah[mt][0], ah[mt][1], ah[mt][2], ah[mt][3],
                             bl[p][q2], bl[p][q2 + 2]);
                    MMA16816(acc[mt][nt], al[mt][0], al[mt][1], al[mt][2], al[mt][3],
                             bh[p][q2], bh[p][q2 + 2]);
                }
            }
        }
    }

#pragma unroll
    for (int nt = 0; nt < 4; nt++) {
        const int col = n0 + wn * 32 + nt * 8 + (lane & 3) * 2;
        const float2 bv = *(const float2*)&bias[col];
#pragma unroll
        for (int mt = 0; mt < 4; mt++) {
            const int r0 = m0 + wm * 64 + mt * 16 + (lane >> 2);
#pragma unroll
            for (int half = 0; half < 2; half++) {
                const int row = r0 + half * 8;
                float2 v;
                v.x = acc[mt][nt][half * 2 + 0] + bv.x;
                v.y = acc[mt][nt][half * 2 + 1] + bv.y;
                if (MODE == 1) {
                    const int b = row >> 10, sdx = row & (SS - 1);
                    const int h = col >> 6, d = col & (HDD - 1);
                    const size_t idx = (((size_t)(b * HH + h) * SS) + sdx) * HDD + d;
                    __nv_bfloat162 hv, lv;
                    hv.x = __float2bfloat16(v.x);
                    hv.y = __float2bfloat16(v.y);
                    lv.x = __float2bfloat16(v.x - __bfloat162float(hv.x));
                    lv.y = __float2bfloat16(v.y - __bfloat162float(hv.y));
                    *(__nv_bfloat162*)&Chi[idx] = hv;
                    *(__nv_bfloat162*)&Clo[idx] = lv;
                } else {
                    *(float2*)&C[(size_t)row * DD + col] = v;
                }
            }
        }
    }
}

// ============== attention pass 1: rowsum + context (NO W write) ============
#define S_QHI 0
#define S_QLO 18432
#define S_KHI 36864
#define S_KLO 55296
#define S_VHI 73728
#define S_VLO 92160
#define S_PHI 110592
#define S_PLO 145408
#define S_RP  180224
#define S_RI  181248
#define ATTN2_SMEM 181760

__global__ __launch_bounds__(256, 1) void attn_mma_kernel(
    const bf16* __restrict__ Qhi_g, const bf16* __restrict__ Qlo_g,
    const bf16* __restrict__ Khi_g, const bf16* __restrict__ Klo_g,
    const bf16* __restrict__ Vhi_g, const bf16* __restrict__ Vlo_g,
    float* __restrict__ rowinv_g,
    bf16* __restrict__ ctxhi, bf16* __restrict__ ctxlo)
{
    extern __shared__ char sm[];
    const uint32_t sb = smem_u32(sm);
    const int tid  = threadIdx.x;
    const int lane = tid & 31;
    const int wid  = tid >> 5;
    const int wm   = wid & 3;
    const int wn   = wid >> 2;
    const int bh   = blockIdx.y;
    const int qt   = gridDim.x - 1 - blockIdx.x;
    const int q0   = qt * 128;
    const int b    = bh >> 4, h = bh & 15;

    ((float*)(sm + S_RP))[tid] = 0.f;

    {
        const size_t base = ((size_t)bh * SS + q0) * HDD;
#pragma unroll
        for (int i = 0; i < 4; i++) {
            const int e = tid + i * 256;
            const int r = e >> 3, c8 = (e & 7) * 8;
            const uint32_t so = (uint32_t)(r * 144 + c8 * 2);
            *(uint4*)(sm + S_QHI + so) = *(const uint4*)&Qhi_g[base + r * 64 + c8];
            *(uint4*)(sm + S_QLO + so) = *(const uint4*)&Qlo_g[base + r * 64 + c8];
        }
    }

    float accPV[2][4][4];
#pragma unroll
    for (int i = 0; i < 2; i++)
#pragma unroll
        for (int j = 0; j < 4; j++)
#pragma unroll
            for (int q = 0; q < 4; q++) accPV[i][j][q] = 0.f;
    float psum[2][2] = {{0.f, 0.f}, {0.f, 0.f}};

    const int nkt = qt + 1;
    for (int kt = 0; kt < nkt; kt++) {
        __syncthreads();
        {
            const size_t base = ((size_t)bh * SS + kt * 128) * HDD;
#pragma unroll
            for (int i = 0; i < 4; i++) {
                const int e = tid + i * 256;
                const int r = e >> 3, c8 = (e & 7) * 8;
                const size_t g = base + r * 64 + c8;
                const uint32_t so = (uint32_t)(r * 144 + c8 * 2);
                *(uint4*)(sm + S_KHI + so) = *(const uint4*)&Khi_g[g];
                *(uint4*)(sm + S_KLO + so) = *(const uint4*)&Klo_g[g];
                *(uint4*)(sm + S_VHI + so) = *(const uint4*)&Vhi_g[g];
                *(uint4*)(sm + S_VLO + so) = *(const uint4*)&Vlo_g[g];
            }
        }
        __syncthreads();

        float acc[2][8][4];
#pragma unroll
        for (int i = 0; i < 2; i++)
#pragma unroll
            for (int j = 0; j < 8; j++)
#pragma unroll
                for (int q = 0; q < 4; q++) acc[i][j][q] = 0.f;

        const uint32_t qa = sb + (uint32_t)((wm * 32 + (lane & 15)) * 144 + (lane >> 4) * 16);
        const uint32_t ka = sb + (uint32_t)((wn * 64 + (lane & 15)) * 144 + (lane >> 4) * 16);
#pragma unroll
        for (int ks = 0; ks < 4; ks++) {
            uint32_t ahi[2][4], alo[2][4], bhi[4][4], blo[4][4];
#pragma unroll
            for (int mt = 0; mt < 2; mt++) {
                const uint32_t ad = qa + (uint32_t)(mt * 16 * 144 + ks * 32);
                LDSM4(ahi[mt][0], ahi[mt][1], ahi[mt][2], ahi[mt][3], ad + S_QHI);
                LDSM4(alo[mt][0], alo[mt][1], alo[mt][2], alo[mt][3], ad + S_QLO);
            }
#pragma unroll
            for (int nt = 0; nt < 4; nt++) {
                const uint32_t bd = ka + (uint32_t)(nt * 16 * 144 + ks * 32);
                LDSM4(bhi[nt][0], bhi[nt][1], bhi[nt][2], bhi[nt][3], bd + S_KHI);
                LDSM4(blo[nt][0], blo[nt][1], blo[nt][2], blo[nt][3], bd + S_KLO);
            }
#pragma unroll
            for (int mt = 0; mt < 2; mt++)
#pragma unroll
                for (int nt = 0; nt < 4; nt++)
#pragma unroll
                    for (int hh = 0; hh < 2; hh++) {
                        float* c = acc[mt][nt * 2 + hh];
                        MMA16816(c, ahi[mt][0], ahi[mt][1], ahi[mt][2], ahi[mt][3],
                                 bhi[nt][hh], bhi[nt][hh + 2]);
                        MMA16816(c, ahi[mt][0], ahi[mt][1], ahi[mt][2], ahi[mt][3],
                                 blo[nt][hh], blo[nt][hh + 2]);
                        MMA16816(c, alo[mt][0], alo[mt][1], alo[mt][2], alo[mt][3],
                                 bhi[nt][hh], bhi[nt][hh + 2]);
                    }
        }

#pragma unroll
        for (int mt = 0; mt < 2; mt++)
#pragma unroll
            for (int half = 0; half < 2; half++) {
                const int lrow = wm * 32 + mt * 16 + (lane >> 2) + half * 8;
                const int grow = q0 + lrow;
                float s = 0.f;
#pragma unroll
                for (int nt = 0; nt < 8; nt++) {
                    const float v0 = acc[mt][nt][half * 2 + 0];
                    const float v1 = acc[mt][nt][half * 2 + 1];
                    const int gc = kt * 128 + wn * 64 + nt * 8 + (lane & 3) * 2;
                    const float e0 = (gc     <= grow) ? __expf(v0 * 0.125f) : 0.f;
                    const float e1 = (gc + 1 <= grow) ? __expf(v1 * 0.125f) : 0.f;
                    s += e0 + e1;
                    const int lcol = wn * 64 + nt * 8 + (lane & 3) * 2;
                    __nv_bfloat162 hv, lv;
                    hv.x = __float2bfloat16(e0);
                    hv.y = __float2bfloat16(e1);
                    lv.x = __float2bfloat16(e0 - __bfloat162float(hv.x));
                    lv.y = __float2bfloat16(e1 - __bfloat162float(hv.y));
                    *(__nv_bfloat162*)(sm + S_PHI + lrow * 272 + lcol * 2) = hv;
                    *(__nv_bfloat162*)(sm + S_PLO + lrow * 272 + lcol * 2) = lv;
                }
                psum[mt][half] += s;
            }
        __syncthreads();

#pragma unroll
        for (int ks = 0; ks < 8; ks++) {
            uint32_t phr[2][4], plr[2][4], vhr[2][4], vlr[2][4];
#pragma unroll
            for (int mt = 0; mt < 2; mt++) {
                const uint32_t ad = sb + (uint32_t)((wm * 32 + mt * 16 + (lane & 15)) * 272
                                                    + ks * 32 + (lane >> 4) * 16);
                LDSM4(phr[mt][0], phr[mt][1], phr[mt][2], phr[mt][3], ad + S_PHI);
                LDSM4(plr[mt][0], plr[mt][1], plr[mt][2], plr[mt][3], ad + S_PLO);
            }
#pragma unroll
            for (int nt16 = 0; nt16 < 2; nt16++) {
                const uint32_t va = sb + (uint32_t)(
                    (ks * 16 + ((lane >> 4) & 1) * 8 + (lane & 7)) * 144
                    + (wn * 32 + nt16 * 16 + ((lane >> 3) & 1) * 8) * 2);
                LDSM4T(vhr[nt16][0], vhr[nt16][1], vhr[nt16][2], vhr[nt16][3], va + S_VHI);
                LDSM4T(vlr[nt16][0], vlr[nt16][1], vlr[nt16][2], vlr[nt16][3], va + S_VLO);
            }
#pragma unroll
            for (int mt = 0; mt < 2; mt++)
#pragma unroll
                for (int j = 0; j < 4; j++) {
                    const int nt16 = j >> 1, hh = j & 1;
                    float* c = accPV[mt][j];
                    MMA16816(c, phr[mt][0], phr[mt][1], phr[mt][2], phr[mt][3],
                             vhr[nt16][hh], vhr[nt16][hh + 2]);
                    MMA16816(c, phr[mt][0], phr[mt][1], phr[mt][2], phr[mt][3],
                             vlr[nt16][hh], vlr[nt16][hh + 2]);
                    MMA16816(c, plr[mt][0], plr[mt][1], plr[mt][2], plr[mt][3],
                             vhr[nt16][hh], vhr[nt16][hh + 2]);
                }
        }
    }

#pragma unroll
    for (int mt = 0; mt < 2; mt++)
#pragma unroll
        for (int half = 0; half < 2; half++) {
            float v = psum[mt][half];
            v += __shfl_xor_sync(~0u, v, 1);
            v += __shfl_xor_sync(~0u, v, 2);
            if ((lane & 3) == 0) {
                const int lrow = wm * 32 + mt * 16 + (lane >> 2) + half * 8;
                ((float*)(sm + S_RP))[wn * 128 + lrow] = v;
            }
        }
    __syncthreads();
    if (tid < 128) {
        const float s = ((float*)(sm + S_RP))[tid] + ((float*)(sm + S_RP))[128 + tid];
        const float inv = 1.0f / s;
        ((float*)(sm + S_RI))[tid] = inv;
        rowinv_g[(size_t)bh * SS + q0 + tid] = inv;
    }
    __syncthreads();

#pragma unroll
    for (int mt = 0; mt < 2; mt++)
#pragma unroll
        for (int j = 0; j < 4; j++)
#pragma unroll
            for (int half = 0; half < 2; half++) {
                const int lrow = wm * 32 + mt * 16 + (lane >> 2) + half * 8;
                const float inv = ((float*)(sm + S_RI))[lrow];
                const int qg = q0 + lrow;
                const int d = h * 64 + wn * 32 + j * 8 + (lane & 3) * 2;
                const float ox = accPV[mt][j][half * 2 + 0] * inv;
                const float oy = accPV[mt][j][half * 2 + 1] * inv;
                __nv_bfloat162 hv, lv;
                hv.x = __float2bfloat16(ox);
                hv.y = __float2bfloat16(oy);
                lv.x = __float2bfloat16(ox - __bfloat162float(hv.x));
                lv.y = __float2bfloat16(oy - __bfloat162float(hv.y));
                const size_t idx = ((size_t)(b * SS + qg)) * DD + d;
                *(__nv_bfloat162*)&ctxhi[idx] = hv;
                *(__nv_bfloat162*)&ctxlo[idx] = lv;
            }
}

// ============== W store: recompute scores, normalize, coalesced write ======
// grid (kt=8, qt=8, bh=64), 256 threads. Tile 128x128.
#define WS_QHI 0
#define WS_QLO 18432
#define WS_KHI 36864
#define WS_KLO 55296
#define WS_TILE 73728                     // fp32 [128][132]
#define WS_RI   (WS_TILE + 128 * 132 * 4) // 141312
#define WS_SMEM (WS_RI + 512 + 64)

__global__ __launch_bounds__(256, 1) void wstore_kernel(
    const bf16* __restrict__ Qhi_g, const bf16* __restrict__ Qlo_g,
    const bf16* __restrict__ Khi_g, const bf16* __restrict__ Klo_g,
    const float* __restrict__ rowinv_g, float* __restrict__ wout)
{
    const int kt = blockIdx.x;
    const int qt = blockIdx.y;
    const int bh = blockIdx.z;
    const int q0 = qt * 128, k0 = kt * 128;
    const int tid = threadIdx.x;
    float* wbase = wout + ((size_t)bh * SS + q0) * SS + k0;

    if (kt > qt) {   // fully masked tile: zero store
        const float4 z = {0.f, 0.f, 0.f, 0.f};
#pragma unroll
        for (int i = 0; i < 16; i++) {
            const int idx = tid + i * 256;
            const int r = idx >> 5, c4 = (idx & 31) * 4;
            __stcs((float4*)&wbase[(size_t)r * SS + c4], z);
        }
        return;
    }

    extern __shared__ char sm[];
    const uint32_t sb = smem_u32(sm);
    const int lane = tid & 31;
    const int wid  = tid >> 5;
    const int wm   = wid & 3;
    const int wn   = wid >> 2;

    {
        const size_t qb = ((size_t)bh * SS + q0) * HDD;
        const size_t kb = ((size_t)bh * SS + k0) * HDD;
#pragma unroll
        for (int i = 0; i < 4; i++) {
            const int e = tid + i * 256;
            const int r = e >> 3, c8 = (e & 7) * 8;
            const uint32_t so = (uint32_t)(r * 144 + c8 * 2);
            *(uint4*)(sm + WS_QHI + so) = *(const uint4*)&Qhi_g[qb + r * 64 + c8];
            *(uint4*)(sm + WS_QLO + so) = *(const uint4*)&Qlo_g[qb + r * 64 + c8];
            *(uint4*)(sm + WS_KHI + so) = *(const uint4*)&Khi_g[kb + r * 64 + c8];
            *(uint4*)(sm + WS_KLO + so) = *(const uint4*)&Klo_g[kb + r * 64 + c8];
        }
        if (tid < 128)
            ((float*)(sm + WS_RI))[tid] = rowinv_g[(size_t)bh * SS + q0 + tid];
    }
    __syncthreads();

    float acc[2][8][4];
#pragma unroll
    for (int i = 0; i < 2; i++)
#pragma unroll
        for (int j = 0; j < 8; j++)
#pragma unroll
            for (int q = 0; q < 4; q++) acc[i][j][q] = 0.f;

    const uint32_t qa = sb + (uint32_t)((wm * 32 + (lane & 15)) * 144 + (lane >> 4) * 16);
    const uint32_t ka = sb + (uint32_t)((wn * 64 + (lane & 15)) * 144 + (lane >> 4) * 16);
#pragma unroll
    for (int ks = 0; ks < 4; ks++) {
        uint32_t ahi[2][4], alo[2][4], bhi[4][4], blo[4][4];
#pragma unroll
        for (int mt = 0; mt < 2; mt++) {
            const uint32_t ad = qa + (uint32_t)(mt * 16 * 144 + ks * 32);
            LDSM4(ahi[mt][0], ahi[mt][1], ahi[mt][2], ahi[mt][3], ad + WS_QHI);
            LDSM4(alo[mt][0], alo[mt][1], alo[mt][2], alo[mt][3], ad + WS_QLO);
        }
#pragma unroll
        for (int nt = 0; nt < 4; nt++) {
            const uint32_t bd = ka + (uint32_t)(nt * 16 * 144 + ks * 32);
            LDSM4(bhi[nt][0], bhi[nt][1], bhi[nt][2], bhi[nt][3], bd + WS_KHI);
            LDSM4(blo[nt][0], blo[nt][1], blo[nt][2], blo[nt][3], bd + WS_KLO);
        }
#pragma unroll
        for (int mt = 0; mt < 2; mt++)
#pragma unroll
            for (int nt = 0; nt < 4; nt++)
#pragma unroll
                for (int hh = 0; hh < 2; hh++) {
                    float* c = acc[mt][nt * 2 + hh];
                    MMA16816(c, ahi[mt][0], ahi[mt][1], ahi[mt][2], ahi[mt][3],
                             bhi[nt][hh], bhi[nt][hh + 2]);
                    MMA16816(c, ahi[mt][0], ahi[mt][1], ahi[mt][2], ahi[mt][3],
                             blo[nt][hh], blo[nt][hh + 2]);
                    MMA16816(c, alo[mt][0], alo[mt][1], alo[mt][2], alo[mt][3],
                             bhi[nt][hh], bhi[nt][hh + 2]);
                }
    }

    // exp * rowinv, stage into smem tile
    float* wt = (float*)(sm + WS_TILE);
#pragma unroll
    for (int mt = 0; mt < 2; mt++)
#pragma unroll
        for (int half = 0; half < 2; half++) {
            const int lrow = wm * 32 + mt * 16 + (lane >> 2) + half * 8;
            const int grow = q0 + lrow;
            const float inv = ((float*)(sm + WS_RI))[lrow];
#pragma unroll
            for (int nt = 0; nt < 8; nt++) {
                const int lcol = wn * 64 + nt * 8 + (lane & 3) * 2;
                const int gc = k0 + lcol;
                const float v0 = acc[mt][nt][half * 2 + 0];
                const float v1 = acc[mt][nt][half * 2 + 1];
                float2 w2;
                w2.x = (gc     <= grow) ? __expf(v0 * 0.125f) * inv : 0.f;
                w2.y = (gc + 1 <= grow) ? __expf(v1 * 0.125f) * inv : 0.f;
                *(float2*)&wt[lrow * 132 + lcol] = w2;
            }
        }
    __syncthreads();

    // coalesced write
#pragma unroll
    for (int i = 0; i < 16; i++) {
        const int idx = tid + i * 256;
        const int r = idx >> 5, c4 = (idx & 31) * 4;
        __stcs((float4*)&wbase[(size_t)r * SS + c4], *(float4*)&wt[r * 132 + c4]);
    }
}

// ============================ launch =======================================
extern "C" void kernel_launch(void* const* d_in, const int* in_sizes, int n_in,
                              void* d_out, int out_size)
{
    const float* q  = (const float*)d_in[0];
    const float* k  = (const float*)d_in[1];
    const float* v  = (const float*)d_in[2];
    const float* Wq = (const float*)d_in[4];
    const float* bq = (const float*)d_in[5];
    const float* Wk = (const float*)d_in[6];
    const float* bk = (const float*)d_in[7];
    const float* Wv = (const float*)d_in[8];
    const float* bv = (const float*)d_in[9];
    const float* Wo = (const float*)d_in[10];
    const float* bo = (const float*)d_in[11];

    float* out = (float*)d_out;

    float *wscr, *rowinv;
    bf16 *Qhi, *Qlo, *Khi, *Klo, *Vhi, *Vlo, *inhi, *inlo, *WThi, *WTlo, *ctxhi, *ctxlo;
    cudaGetSymbolAddress((void**)&wscr,   g_wscratch);
    cudaGetSymbolAddress((void**)&rowinv, g_rowinv);
    cudaGetSymbolAddress((void**)&Qhi,    g_Qhi);
    cudaGetSymbolAddress((void**)&Qlo,    g_Qlo);
    cudaGetSymbolAddress((void**)&Khi,    g_Khi);
    cudaGetSymbolAddress((void**)&Klo,    g_Klo);
    cudaGetSymbolAddress((void**)&Vhi,    g_Vhi);
    cudaGetSymbolAddress((void**)&Vlo,    g_Vlo);
    cudaGetSymbolAddress((void**)&inhi,   g_inhi);
    cudaGetSymbolAddress((void**)&inlo,   g_inlo);
    cudaGetSymbolAddress((void**)&WThi,   g_WThi);
    cudaGetSymbolAddress((void**)&WTlo,   g_WTlo);
    cudaGetSymbolAddress((void**)&ctxhi,  g_ctxhi);
    cudaGetSymbolAddress((void**)&ctxlo,  g_ctxlo);

    const size_t MD = (size_t)MM * DD;
    const size_t D2 = (size_t)DD * DD;

    float* wout = ((size_t)out_size >= OUT_ELEMS + W_ELEMS) ? (out + OUT_ELEMS) : wscr;

    cudaFuncSetAttribute(gemm_bf16_kernel<0>,
                         cudaFuncAttributeMaxDynamicSharedMemorySize, GEMM_SMEM3);
    cudaFuncSetAttribute(gemm_bf16_kernel<1>,
                         cudaFuncAttributeMaxDynamicSharedMemorySize, GEMM_SMEM3);
    cudaFuncSetAttribute(attn_mma_kernel,
                         cudaFuncAttributeMaxDynamicSharedMemorySize, ATTN2_SMEM);
    cudaFuncSetAttribute(wstore_kernel,
                         cudaFuncAttributeMaxDynamicSharedMemorySize, WS_SMEM);

    split_kernel<<<MD / (256 * 8), 256>>>(q, inhi + 0 * MD, inlo + 0 * MD);
    split_kernel<<<MD / (256 * 8), 256>>>(k, inhi + 1 * MD, inlo + 1 * MD);
    split_kernel<<<MD / (256 * 8), 256>>>(v, inhi + 2 * MD, inlo + 2 * MD);
    const dim3 gtr(32, 32);
    transpose_split_kernel<<<gtr, 256>>>(Wq, WThi + 0 * D2, WTlo + 0 * D2);
    transpose_split_kernel<<<gtr, 256>>>(Wk, WThi + 1 * D2, WTlo + 1 * D2);
    transpose_split_kernel<<<gtr, 256>>>(Wv, WThi + 2 * D2, WTlo + 2 * D2);
    transpose_split_kernel<<<gtr, 256>>>(Wo, WThi + 3 * D2, WTlo + 3 * D2);

    const dim3 ggemm(DD / 256, MM / 128);
    gemm_bf16_kernel<1><<<ggemm, 512, GEMM_SMEM3>>>(
        inhi + 0 * MD, inlo + 0 * MD, WThi + 0 * D2, WTlo + 0 * D2, bq, nullptr, Qhi, Qlo);
    gemm_bf16_kernel<1><<<ggemm, 512, GEMM_SMEM3>>>(
        inhi + 1 * MD, inlo + 1 * MD, WThi + 1 * D2, WTlo + 1 * D2, bk, nullptr, Khi, Klo);
    gemm_bf16_kernel<1><<<ggemm, 512, GEMM_SMEM3>>>(
        inhi + 2 * MD, inlo + 2 * MD, WThi + 2 * D2, WTlo + 2 * D2, bv, nullptr, Vhi, Vlo);

    attn_mma_kernel<<<dim3(SS / 128, BHT), 256, ATTN2_SMEM>>>(
        Qhi, Qlo, Khi, Klo, Vhi, Vlo, rowinv, ctxhi, ctxlo);

    wstore_kernel<<<dim3(8, 8, BHT), 256, WS_SMEM>>>(
        Qhi, Qlo, Khi, Klo, rowinv, wout);

    gemm_bf16_kernel<0><<<ggemm, 512, GEMM_SMEM3>>>(
        ctxhi, ctxlo, WThi + 3 * D2, WTlo + 3 * D2, bo, out, nullptr, nullptr);
}

// round 10
// speedup vs baseline: 1.1415x; 1.1415x over previous
#include <cuda_runtime.h>
#include <cuda_bf16.h>
#include <cstddef>
#include <cstdint>

#define BB   4
#define SS   1024
#define DD   1024
#define HH   16
#define HDD  64
#define MM   (BB * SS)
#define BHT  (BB * HH)
#define OUT_ELEMS    ((size_t)BB * SS * DD)
#define W_ELEMS      ((size_t)BB * HH * SS * SS)

typedef __nv_bfloat16 bf16;

__device__ float g_wscratch[W_ELEMS];
__device__ float g_rowinv[BHT * SS];
__device__ bf16 g_Qhi[BHT * SS * HDD];
__device__ bf16 g_Qlo[BHT * SS * HDD];
__device__ bf16 g_Khi[BHT * SS * HDD];
__device__ bf16 g_Klo[BHT * SS * HDD];
__device__ bf16 g_Vhi[BHT * SS * HDD];
__device__ bf16 g_Vlo[BHT * SS * HDD];
__device__ bf16 g_inhi[3][MM * DD];
__device__ bf16 g_inlo[3][MM * DD];
__device__ bf16 g_WThi[4][DD * DD];
__device__ bf16 g_WTlo[4][DD * DD];
__device__ bf16 g_ctxhi[MM * DD];
__device__ bf16 g_ctxlo[MM * DD];

__device__ __forceinline__ uint32_t smem_u32(const void* p) {
    uint32_t a;
    asm("{ .reg .u64 t; cvta.to.shared.u64 t, %1; cvt.u32.u64 %0, t; }"
        : "=r"(a) : "l"(p));
    return a;
}

#define LDSM4(r0, r1, r2, r3, a)                                            \
    asm volatile("ldmatrix.sync.aligned.m8n8.x4.shared.b16 {%0,%1,%2,%3}, [%4];" \
        : "=r"(r0), "=r"(r1), "=r"(r2), "=r"(r3) : "r"(a))
#define LDSM4T(r0, r1, r2, r3, a)                                           \
    asm volatile("ldmatrix.sync.aligned.m8n8.x4.trans.shared.b16 {%0,%1,%2,%3}, [%4];" \
        : "=r"(r0), "=r"(r1), "=r"(r2), "=r"(r3) : "r"(a))
#define MMA16816(c, a0, a1, a2, a3, b0, b1)                                 \
    asm volatile("mma.sync.aligned.m16n8k16.row.col.f32.bf16.bf16.f32 "     \
        "{%0,%1,%2,%3}, {%4,%5,%6,%7}, {%8,%9}, {%0,%1,%2,%3};"             \
        : "+f"((c)[0]), "+f"((c)[1]), "+f"((c)[2]), "+f"((c)[3])            \
        : "r"(a0), "r"(a1), "r"(a2), "r"(a3), "r"(b0), "r"(b1))
#define CP16(smaddr, gptr)                                                  \
    asm volatile("cp.async.cg.shared.global [%0], [%1], 16;"                \
        :: "r"(smaddr), "l"(gptr))
#define CP_COMMIT() asm volatile("cp.async.commit_group;" ::: "memory")
#define CP_WAIT1()  asm volatile("cp.async.wait_group 1;"  ::: "memory")

__device__ __forceinline__ void split4(float4 v, uint2& hi, uint2& lo) {
    __nv_bfloat162 h0 = __float22bfloat162_rn(make_float2(v.x, v.y));
    __nv_bfloat162 h1 = __float22bfloat162_rn(make_float2(v.z, v.w));
    float2 f0 = __bfloat1622float2(h0);
    float2 f1 = __bfloat1622float2(h1);
    __nv_bfloat162 l0 = __float22bfloat162_rn(make_float2(v.x - f0.x, v.y - f0.y));
    __nv_bfloat162 l1 = __float22bfloat162_rn(make_float2(v.z - f1.x, v.w - f1.y));
    hi.x = *(uint32_t*)&h0; hi.y = *(uint32_t*)&h1;
    lo.x = *(uint32_t*)&l0; lo.y = *(uint32_t*)&l1;
}

// pack two fp32 into bf16x2 hi + residual lo
__device__ __forceinline__ void pack_hl(float a, float b, uint32_t& hi, uint32_t& lo) {
    __nv_bfloat162 h = __float22bfloat162_rn(make_float2(a, b));
    float2 f = __bfloat1622float2(h);
    __nv_bfloat162 l = __float22bfloat162_rn(make_float2(a - f.x, b - f.y));
    hi = *(uint32_t*)&h;
    lo = *(uint32_t*)&l;
}

// ===================== batched input split =================================
__global__ __launch_bounds__(256) void split_kernel(
    const float* __restrict__ s0, const float* __restrict__ s1,
    const float* __restrict__ s2, bf16* __restrict__ hib, bf16* __restrict__ lob)
{
    const float* src = (blockIdx.y == 0) ? s0 : (blockIdx.y == 1) ? s1 : s2;
    const size_t off = (size_t)blockIdx.y * MM * DD;
    const size_t base = ((size_t)blockIdx.x * 256 + threadIdx.x) * 8;
    float4 a = *(const float4*)&src[base];
    float4 b = *(const float4*)&src[base + 4];
    uint2 h0, l0, h1, l1;
    split4(a, h0, l0);
    split4(b, h1, l1);
    uint4 hv; hv.x = h0.x; hv.y = h0.y; hv.z = h1.x; hv.w = h1.y;
    uint4 lv; lv.x = l0.x; lv.y = l0.y; lv.z = l1.x; lv.w = l1.y;
    *(uint4*)&hib[off + base] = hv;
    *(uint4*)&lob[off + base] = lv;
}

// ===================== batched weight transpose + split ====================
__global__ __launch_bounds__(256) void transpose_split_kernel(
    const float* __restrict__ w0, const float* __restrict__ w1,
    const float* __restrict__ w2, const float* __restrict__ w3,
    bf16* __restrict__ dhib, bf16* __restrict__ dlob)
{
    const float* src = (blockIdx.z == 0) ? w0 : (blockIdx.z == 1) ? w1
                     : (blockIdx.z == 2) ? w2 : w3;
    bf16* dhi = dhib + (size_t)blockIdx.z * DD * DD;
    bf16* dlo = dlob + (size_t)blockIdx.z * DD * DD;
    __shared__ float t[32][33];
    const int tid = threadIdx.x;
    const int x = blockIdx.x * 32 + (tid & 31);
    const int y0 = blockIdx.y * 32 + (tid >> 5);
#pragma unroll
    for (int r = 0; r < 4; r++)
        t[(tid >> 5) + r * 8][tid & 31] = src[(size_t)(y0 + r * 8) * DD + x];
    __syncthreads();
    const int x2 = blockIdx.y * 32 + (tid & 31);
    const int y2 = blockIdx.x * 32 + (tid >> 5);
#pragma unroll
    for (int r = 0; r < 4; r++) {
        const float v = t[tid & 31][(tid >> 5) + r * 8];
        const bf16 h = __float2bfloat16(v);
        const bf16 l = __float2bfloat16(v - __bfloat162float(h));
        dhi[(size_t)(y2 + r * 8) * DD + x2] = h;
        dlo[(size_t)(y2 + r * 8) * DD + x2] = l;
    }
}

// ===================== bf16x3 GEMM (R8, unchanged) =========================
#define GA_HI 0
#define GA_LO 10240
#define GB_HI 20480
#define GB_LO 40960
#define STAGE_B 61440
#define GEMM_SMEM3 (3 * STAGE_B)

template <int MODE>
__global__ __launch_bounds__(512, 1) void gemm_bf16_kernel(
    const bf16* __restrict__ Ahi, const bf16* __restrict__ Alo,
    const bf16* __restrict__ Bhi, const bf16* __restrict__ Blo,
    const float* __restrict__ bias, float* __restrict__ C,
    bf16* __restrict__ Chi, bf16* __restrict__ Clo)
{
    extern __shared__ char smem[];
    const uint32_t sb = smem_u32(smem);
    const int tid  = threadIdx.x;
    const int wid  = tid >> 5;
    const int lane = tid & 31;
    const int wm   = wid & 1;
    const int wn   = wid >> 1;
    const int m0 = blockIdx.y * 128;
    const int n0 = blockIdx.x * 256;

    float acc[4][4][4];
#pragma unroll
    for (int i = 0; i < 4; i++)
#pragma unroll
        for (int j = 0; j < 4; j++)
#pragma unroll
            for (int q = 0; q < 4; q++) acc[i][j][q] = 0.f;

    auto issue = [&](int c) {
        if (c < 32) {
            const uint32_t st = sb + (c % 3) * STAGE_B;
            const int k0 = c * 32;
            {
                const int row = tid >> 2, g = tid & 3;
                const size_t ga = (size_t)(m0 + row) * DD + k0 + g * 8;
                const uint32_t so = (uint32_t)(row * 80 + g * 16);
                CP16(st + GA_HI + so, Ahi + ga);
                CP16(st + GA_LO + so, Alo + ga);
            }
#pragma unroll
            for (int r = 0; r < 2; r++) {
                const int idx = tid + r * 512;
                const int row = idx >> 2, g = idx & 3;
                const size_t gb = (size_t)(n0 + row) * DD + k0 + g * 8;
                const uint32_t so = (uint32_t)(row * 80 + g * 16);
                CP16(st + GB_HI + so, Bhi + gb);
                CP16(st + GB_LO + so, Blo + gb);
            }
        }
        CP_COMMIT();
    };

    issue(0);
    issue(1);

    const uint32_t a_off = (uint32_t)((wm * 64 + (lane & 15)) * 80 + (lane >> 4) * 16);
    const uint32_t b_off = (uint32_t)((wn * 32 + (lane & 15)) * 80 + (lane >> 4) * 16);

    for (int c = 0; c < 32; c++) {
        CP_WAIT1();
        __syncthreads();
        issue(c + 2);

        const uint32_t bb = sb + (c % 3) * STAGE_B;
#pragma unroll
        for (int ks = 0; ks < 2; ks++) {
            uint32_t ah[4][4], al[4][4], bh[2][4], bl[2][4];
#pragma unroll
            for (int mt = 0; mt < 4; mt++) {
                const uint32_t ad = bb + a_off + (uint32_t)(mt * 16 * 80 + ks * 32);
                LDSM4(ah[mt][0], ah[mt][1], ah[mt][2], ah[mt][3], ad + GA_HI);
                LDSM4(al[mt][0], al[mt][1], al[mt][2], al[mt][3], ad + GA_LO);
            }
#pragma unroll
            for (int p = 0; p < 2; p++) {
                const uint32_t bd = bb + b_off + (uint32_t)(p * 16 * 80 + ks * 32);
                LDSM4(bh[p][0], bh[p][1], bh[p][2], bh[p][3], bd + GB_HI);
                LDSM4(bl[p][0], bl[p][1], bl[p][2], bl[p][3], bd + GB_LO);
            }
#pragma unroll
            for (int mt = 0; mt < 4; mt++) {
#pragma unroll
                for (int nt = 0; nt < 4; nt++) {
                    const int p = nt >> 1, q2 = nt & 1;
                    MMA16816(acc[mt][nt], ah[mt][0], ah[mt][1], ah[mt][2], ah[mt][3],
                             bh[p][q2], bh[p][q2 + 2]);
                    MMA16816(acc[mt][nt], ah[mt][0], ah[mt][1], ah[mt][2], ah[mt][3],
                             bl[p][q2], bl[p][q2 + 2]);
                    MMA16816(acc[mt][nt], al[mt][0], al[mt][1], al[mt][2], al[mt][3],
                             bh[p][q2], bh[p][q2 + 2]);
                }
            }
        }
    }

#pragma unroll
    for (int nt = 0; nt < 4; nt++) {
        const int col = n0 + wn * 32 + nt * 8 + (lane & 3) * 2;
        const float2 bv = *(const float2*)&bias[col];
#pragma unroll
        for (int mt = 0; mt < 4; mt++) {
            const int r0 = m0 + wm * 64 + mt * 16 + (lane >> 2);
#pragma unroll
            for (int half = 0; half < 2; half++) {
                const int row = r0 + half * 8;
                float2 v;
                v.x = acc[mt][nt][half * 2 + 0] + bv.x;
                v.y = acc[mt][nt][half * 2 + 1] + bv.y;
                if (MODE == 1) {
                    const int b = row >> 10, sdx = row & (SS - 1);
                    const int h = col >> 6, d = col & (HDD - 1);
                    const size_t idx = (((size_t)(b * HH + h) * SS) + sdx) * HDD + d;
                    __nv_bfloat162 hv, lv;
                    hv.x = __float2bfloat16(v.x);
                    hv.y = __float2bfloat16(v.y);
                    lv.x = __float2bfloat16(v.x - __bfloat162float(hv.x));
                    lv.y = __float2bfloat16(v.y - __bfloat162float(hv.y));
                    *(__nv_bfloat162*)&Chi[idx] = hv;
                    *(__nv_bfloat162*)&Clo[idx] = lv;
                } else {
                    *(float2*)&C[(size_t)row * DD + col] = v;
                }
            }
        }
    }
}

// ======== attention: register-P FA2 style, cp.async double-buffered KV =====
// 256 thr, 8 warps; warp w owns q-rows w*16..w*16+15, all 128 k-cols.
// smem: Qhi/Qlo [128][72]b16, KV double buffer (Khi,Klo,Vhi,Vlo each [128][72]).
#define AT_QHI 0
#define AT_QLO 18432
#define AT_KV0 36864
#define AT_KVSZ 73728
#define AT_KHI 0
#define AT_KLO 18432
#define AT_VHI 36864
#define AT_VLO 55296
#define ATTN3_SMEM (AT_KV0 + 2 * AT_KVSZ)   // 184320

__global__ __launch_bounds__(256, 1) void attn_mma_kernel(
    const bf16* __restrict__ Qhi_g, const bf16* __restrict__ Qlo_g,
    const bf16* __restrict__ Khi_g, const bf16* __restrict__ Klo_g,
    const bf16* __restrict__ Vhi_g, const bf16* __restrict__ Vlo_g,
    float* __restrict__ wout, float* __restrict__ rowinv_g,
    bf16* __restrict__ ctxhi, bf16* __restrict__ ctxlo)
{
    extern __shared__ char sm[];
    const uint32_t sb = smem_u32(sm);
    const int tid  = threadIdx.x;
    const int lane = tid & 31;
    const int wid  = tid >> 5;
    const int r0   = wid * 16;
    const int bh   = blockIdx.y;
    const int qt   = gridDim.x - 1 - blockIdx.x;   // heavy first
    const int q0   = qt * 128;
    const int b    = bh >> 4, h = bh & 15;
    const int nkt  = qt + 1;

    // load Q tile (plain stores; visible after first sync pair)
    {
        const size_t base = ((size_t)bh * SS + q0) * HDD;
#pragma unroll
        for (int i = 0; i < 4; i++) {
            const int e = tid + i * 256;
            const int r = e >> 3, c8 = (e & 7) * 8;
            const uint32_t so = (uint32_t)(r * 144 + c8 * 2);
            *(uint4*)(sm + AT_QHI + so) = *(const uint4*)&Qhi_g[base + r * 64 + c8];
            *(uint4*)(sm + AT_QLO + so) = *(const uint4*)&Qlo_g[base + r * 64 + c8];
        }
    }

    auto issue = [&](int kt) {
        if (kt < nkt) {
            const uint32_t kvb = sb + AT_KV0 + (kt & 1) * AT_KVSZ;
            const size_t gbase = ((size_t)bh * SS + kt * 128) * HDD;
#pragma unroll
            for (int i = 0; i < 4; i++) {
                const int e = tid + i * 256;
                const int r = e >> 3, g = e & 7;
                const uint32_t off = (uint32_t)(r * 144 + g * 16);
                const size_t go = gbase + r * 64 + g * 8;
                CP16(kvb + AT_KHI + off, Khi_g + go);
                CP16(kvb + AT_KLO + off, Klo_g + go);
                CP16(kvb + AT_VHI + off, Vhi_g + go);
                CP16(kvb + AT_VLO + off, Vlo_g + go);
            }
        }
        CP_COMMIT();
    };
    issue(0);

    float pv[8][4];
#pragma unroll
    for (int i = 0; i < 8; i++)
#pragma unroll
        for (int j = 0; j < 4; j++) pv[i][j] = 0.f;
    float ps0 = 0.f, ps1 = 0.f;

    const int grow0 = q0 + r0 + (lane >> 2);
    const int grow1 = grow0 + 8;
    const uint32_t qa = sb + AT_QHI + (uint32_t)((r0 + (lane & 15)) * 144 + (lane >> 4) * 16);

    for (int kt = 0; kt < nkt; kt++) {
        __syncthreads();          // all warps done reading buf kt&1 from iter kt-2
        issue(kt + 1);
        CP_WAIT1();
        __syncthreads();          // buf kt&1 visible to all
        const uint32_t kvb = sb + AT_KV0 + (kt & 1) * AT_KVSZ;

        // ---- scores: m16 x n128 per warp ----
        float accE[16][4];
#pragma unroll
        for (int i = 0; i < 16; i++)
#pragma unroll
            for (int j = 0; j < 4; j++) accE[i][j] = 0.f;

#pragma unroll
        for (int ks = 0; ks < 4; ks++) {
            uint32_t ah[4], al[4];
            LDSM4(ah[0], ah[1], ah[2], ah[3], qa + ks * 32);
            LDSM4(al[0], al[1], al[2], al[3], qa + (AT_QLO - AT_QHI) + ks * 32);
#pragma unroll
            for (int nb = 0; nb < 8; nb++) {
                const uint32_t ka = kvb + AT_KHI +
                    (uint32_t)((nb * 16 + (lane & 15)) * 144 + ks * 32 + (lane >> 4) * 16);
                uint32_t kh4[4], kl4[4];
                LDSM4(kh4[0], kh4[1], kh4[2], kh4[3], ka);
                LDSM4(kl4[0], kl4[1], kl4[2], kl4[3], ka + (AT_KLO - AT_KHI));
#pragma unroll
                for (int hh = 0; hh < 2; hh++) {
                    float* c = accE[nb * 2 + hh];
                    MMA16816(c, ah[0], ah[1], ah[2], ah[3], kh4[hh], kh4[hh + 2]);
                    MMA16816(c, ah[0], ah[1], ah[2], ah[3], kl4[hh], kl4[hh + 2]);
                    MMA16816(c, al[0], al[1], al[2], al[3], kh4[hh], kh4[hh + 2]);
                }
            }
        }

        // ---- exp + mask + unnormalized W write + rowsum ----
#pragma unroll
        for (int nt = 0; nt < 16; nt++) {
            const int gc = kt * 128 + nt * 8 + (lane & 3) * 2;
            float e00 = (gc     <= grow0) ? __expf(accE[nt][0] * 0.125f) : 0.f;
            float e01 = (gc + 1 <= grow0) ? __expf(accE[nt][1] * 0.125f) : 0.f;
            float e10 = (gc     <= grow1) ? __expf(accE[nt][2] * 0.125f) : 0.f;
            float e11 = (gc + 1 <= grow1) ? __expf(accE[nt][3] * 0.125f) : 0.f;
            accE[nt][0] = e00; accE[nt][1] = e01;
            accE[nt][2] = e10; accE[nt][3] = e11;
            ps0 += e00 + e01;
            ps1 += e10 + e11;
            float2 w0; w0.x = e00; w0.y = e01;
            float2 w1; w1.x = e10; w1.y = e11;
            __stcs((float2*)&wout[((size_t)bh * SS + grow0) * SS + gc], w0);
            __stcs((float2*)&wout[((size_t)bh * SS + grow1) * SS + gc], w1);
        }

        // ---- PV: P fragments straight from registers ----
#pragma unroll
        for (int j = 0; j < 8; j++) {
            uint32_t ph[4], pl[4];
            pack_hl(accE[2 * j][0],     accE[2 * j][1],     ph[0], pl[0]);
            pack_hl(accE[2 * j][2],     accE[2 * j][3],     ph[1], pl[1]);
            pack_hl(accE[2 * j + 1][0], accE[2 * j + 1][1], ph[2], pl[2]);
            pack_hl(accE[2 * j + 1][2], accE[2 * j + 1][3], ph[3], pl[3]);
#pragma unroll
            for (int nd = 0; nd < 4; nd++) {
                const uint32_t va = kvb + AT_VHI + (uint32_t)(
                    (j * 16 + ((lane >> 4) & 1) * 8 + (lane & 7)) * 144
                    + (nd * 16 + ((lane >> 3) & 1) * 8) * 2);
                uint32_t vh4[4], vl4[4];
                LDSM4T(vh4[0], vh4[1], vh4[2], vh4[3], va);
                LDSM4T(vl4[0], vl4[1], vl4[2], vl4[3], va + (AT_VLO - AT_VHI));
#pragma unroll
                for (int hh = 0; hh < 2; hh++) {
                    float* c = pv[nd * 2 + hh];
                    MMA16816(c, ph[0], ph[1], ph[2], ph[3], vh4[hh], vh4[hh + 2]);
                    MMA16816(c, ph[0], ph[1], ph[2], ph[3], vl4[hh], vl4[hh + 2]);
                    MMA16816(c, pl[0], pl[1], pl[2], pl[3], vh4[hh], vh4[hh + 2]);
                }
            }
        }
    }

    // ---- rowsum reduce within quad (warp owns its rows fully) ----
    ps0 += __shfl_xor_sync(~0u, ps0, 1);
    ps0 += __shfl_xor_sync(~0u, ps0, 2);
    ps1 += __shfl_xor_sync(~0u, ps1, 1);
    ps1 += __shfl_xor_sync(~0u, ps1, 2);
    const float inv0 = 1.0f / ps0;
    const float inv1 = 1.0f / ps1;
    if ((lane & 3) == 0) {
        rowinv_g[(size_t)bh * SS + grow0] = inv0;
        rowinv_g[(size_t)bh * SS + grow1] = inv1;
    }

    // ---- context write (normalized, bf16 hi/lo) ----
#pragma unroll
    for (int dt = 0; dt < 8; dt++) {
        const int d = h * 64 + dt * 8 + (lane & 3) * 2;
        const float o0x = pv[dt][0] * inv0, o0y = pv[dt][1] * inv0;
        const float o1x = pv[dt][2] * inv1, o1y = pv[dt][3] * inv1;
        __nv_bfloat162 hv, lv;
        hv.x = __float2bfloat16(o0x); hv.y = __float2bfloat16(o0y);
        lv.x = __float2bfloat16(o0x - __bfloat162float(hv.x));
        lv.y = __float2bfloat16(o0y - __bfloat162float(hv.y));
        size_t idx = ((size_t)(b * SS + grow0)) * DD + d;
        *(__nv_bfloat162*)&ctxhi[idx] = hv;
        *(__nv_bfloat162*)&ctxlo[idx] = lv;
        hv.x = __float2bfloat16(o1x); hv.y = __float2bfloat16(o1y);
        lv.x = __float2bfloat16(o1x - __bfloat162float(hv.x));
        lv.y = __float2bfloat16(o1y - __bfloat162float(hv.y));
        idx = ((size_t)(b * SS + grow1)) * DD + d;
        *(__nv_bfloat162*)&ctxhi[idx] = hv;
        *(__nv_bfloat162*)&ctxlo[idx] = lv;
    }
}

// ============================ normalize weights ============================
__global__ __launch_bounds__(128) void norm_kernel(
    float* __restrict__ w, const float* __restrict__ rowinv)
{
    const int row = blockIdx.x;
    const int q = row & (SS - 1);
    const float inv = rowinv[row];
    float4* wr = (float4*)(w + (size_t)row * SS);
    const int tid = threadIdx.x;
#pragma unroll
    for (int i = 0; i < 2; i++) {
        const int j = tid + i * 128;
        const int k = j * 4;
        float4 v;
        if (k + 3 <= q) {
            v = wr[j];
            v.x *= inv; v.y *= inv; v.z *= inv; v.w *= inv;
        } else if (k > q) {
            v.x = v.y = v.z = v.w = 0.f;
        } else {
            v = wr[j];
            v.x = (k     <= q) ? v.x * inv : 0.f;
            v.y = (k + 1 <= q) ? v.y * inv : 0.f;
            v.z = (k + 2 <= q) ? v.z * inv : 0.f;
            v.w = (k + 3 <= q) ? v.w * inv : 0.f;
        }
        wr[j] = v;
    }
}

// ============================ launch =======================================
extern "C" void kernel_launch(void* const* d_in, const int* in_sizes, int n_in,
                              void* d_out, int out_size)
{
    const float* q  = (const float*)d_in[0];
    const float* k  = (const float*)d_in[1];
    const float* v  = (const float*)d_in[2];
    const float* Wq = (const float*)d_in[4];
    const float* bq = (const float*)d_in[5];
    const float* Wk = (const float*)d_in[6];
    const float* bk = (const float*)d_in[7];
    const float* Wv = (const float*)d_in[8];
    const float* bv = (const float*)d_in[9];
    const float* Wo = (const float*)d_in[10];
    const float* bo = (const float*)d_in[11];

    float* out = (float*)d_out;

    float *wscr, *rowinv;
    bf16 *Qhi, *Qlo, *Khi, *Klo, *Vhi, *Vlo, *inhi, *inlo, *WThi, *WTlo, *ctxhi, *ctxlo;
    cudaGetSymbolAddress((void**)&wscr,   g_wscratch);
    cudaGetSymbolAddress((void**)&rowinv, g_rowinv);
    cudaGetSymbolAddress((void**)&Qhi,    g_Qhi);
    cudaGetSymbolAddress((void**)&Qlo,    g_Qlo);
    cudaGetSymbolAddress((void**)&Khi,    g_Khi);
    cudaGetSymbolAddress((void**)&Klo,    g_Klo);
    cudaGetSymbolAddress((void**)&Vhi,    g_Vhi);
    cudaGetSymbolAddress((void**)&Vlo,    g_Vlo);
    cudaGetSymbolAddress((void**)&inhi,   g_inhi);
    cudaGetSymbolAddress((void**)&inlo,   g_inlo);
    cudaGetSymbolAddress((void**)&WThi,   g_WThi);
    cudaGetSymbolAddress((void**)&WTlo,   g_WTlo);
    cudaGetSymbolAddress((void**)&ctxhi,  g_ctxhi);
    cudaGetSymbolAddress((void**)&ctxlo,  g_ctxlo);

    const size_t MD = (size_t)MM * DD;
    const size_t D2 = (size_t)DD * DD;

    float* wout = ((size_t)out_size >= OUT_ELEMS + W_ELEMS) ? (out + OUT_ELEMS) : wscr;

    cudaFuncSetAttribute(gemm_bf16_kernel<0>,
                         cudaFuncAttributeMaxDynamicSharedMemorySize, GEMM_SMEM3);
    cudaFuncSetAttribute(gemm_bf16_kernel<1>,
                         cudaFuncAttributeMaxDynamicSharedMemorySize, GEMM_SMEM3);
    cudaFuncSetAttribute(attn_mma_kernel,
                         cudaFuncAttributeMaxDynamicSharedMemorySize, ATTN3_SMEM);

    // launch #1: batched input split, #2: batched weight transpose+split
    split_kernel<<<dim3(MD / (256 * 8), 3), 256>>>(q, k, v, inhi, inlo);
    transpose_split_kernel<<<dim3(32, 32, 4), 256>>>(Wq, Wk, Wv, Wo, WThi, WTlo);

    const dim3 ggemm(DD / 256, MM / 128);
    // launches #3-5
    gemm_bf16_kernel<1><<<ggemm, 512, GEMM_SMEM3>>>(
        inhi + 0 * MD, inlo + 0 * MD, WThi + 0 * D2, WTlo + 0 * D2, bq, nullptr, Qhi, Qlo);
    gemm_bf16_kernel<1><<<ggemm, 512, GEMM_SMEM3>>>(
        inhi + 1 * MD, inlo + 1 * MD, WThi + 1 * D2, WTlo + 1 * D2, bk, nullptr, Khi, Klo);
    gemm_bf16_kernel<1><<<ggemm, 512, GEMM_SMEM3>>>(
        inhi + 2 * MD, inlo + 2 * MD, WThi + 2 * D2, WTlo + 2 * D2, bv, nullptr, Vhi, Vlo);

    // launch #6 (ncu -s 5 -c 1 captures this one)
    attn_mma_kernel<<<dim3(SS / 128, BHT), 256, ATTN3_SMEM>>>(
        Qhi, Qlo, Khi, Klo, Vhi, Vlo, wout, rowinv, ctxhi, ctxlo);

    norm_kernel<<<BHT * SS, 128>>>(wout, rowinv);

    gemm_bf16_kernel<0><<<ggemm, 512, GEMM_SMEM3>>>(
        ctxhi, ctxlo, WThi + 3 * D2, WTlo + 3 * D2, bo, out, nullptr, nullptr);
}

// round 11
// speedup vs baseline: 1.1564x; 1.0131x over previous
#include <cuda_runtime.h>
#include <cuda_bf16.h>
#include <cstddef>
#include <cstdint>

#define BB   4
#define SS   1024
#define DD   1024
#define HH   16
#define HDD  64
#define MM   (BB * SS)
#define BHT  (BB * HH)
#define OUT_ELEMS    ((size_t)BB * SS * DD)
#define W_ELEMS      ((size_t)BB * HH * SS * SS)

typedef __nv_bfloat16 bf16;

__device__ float g_wscratch[W_ELEMS];
__device__ float g_rowinv[BHT * SS];
__device__ bf16 g_Qhi[BHT * SS * HDD];
__device__ bf16 g_Qlo[BHT * SS * HDD];
__device__ bf16 g_Khi[BHT * SS * HDD];
__device__ bf16 g_Klo[BHT * SS * HDD];
__device__ bf16 g_Vhi[BHT * SS * HDD];
__device__ bf16 g_Vlo[BHT * SS * HDD];
__device__ bf16 g_inhi[3][MM * DD];
__device__ bf16 g_inlo[3][MM * DD];
__device__ bf16 g_WThi[4][DD * DD];
__device__ bf16 g_WTlo[4][DD * DD];
__device__ bf16 g_ctxhi[MM * DD];
__device__ bf16 g_ctxlo[MM * DD];

__device__ __forceinline__ uint32_t smem_u32(const void* p) {
    uint32_t a;
    asm("{ .reg .u64 t; cvta.to.shared.u64 t, %1; cvt.u32.u64 %0, t; }"
        : "=r"(a) : "l"(p));
    return a;
}

#define LDSM4(r0, r1, r2, r3, a)                                            \
    asm volatile("ldmatrix.sync.aligned.m8n8.x4.shared.b16 {%0,%1,%2,%3}, [%4];" \
        : "=r"(r0), "=r"(r1), "=r"(r2), "=r"(r3) : "r"(a))
#define LDSM4T(r0, r1, r2, r3, a)                                           \
    asm volatile("ldmatrix.sync.aligned.m8n8.x4.trans.shared.b16 {%0,%1,%2,%3}, [%4];" \
        : "=r"(r0), "=r"(r1), "=r"(r2), "=r"(r3) : "r"(a))
#define MMA16816(c, a0, a1, a2, a3, b0, b1)                                 \
    asm volatile("mma.sync.aligned.m16n8k16.row.col.f32.bf16.bf16.f32 "     \
        "{%0,%1,%2,%3}, {%4,%5,%6,%7}, {%8,%9}, {%0,%1,%2,%3};"             \
        : "+f"((c)[0]), "+f"((c)[1]), "+f"((c)[2]), "+f"((c)[3])            \
        : "r"(a0), "r"(a1), "r"(a2), "r"(a3), "r"(b0), "r"(b1))
#define CP16(smaddr, gptr)                                                  \
    asm volatile("cp.async.cg.shared.global [%0], [%1], 16;"                \
        :: "r"(smaddr), "l"(gptr))
#define CP_COMMIT() asm volatile("cp.async.commit_group;" ::: "memory")
#define CP_WAIT1()  asm volatile("cp.async.wait_group 1;"  ::: "memory")

__device__ __forceinline__ void split4(float4 v, uint2& hi, uint2& lo) {
    __nv_bfloat162 h0 = __float22bfloat162_rn(make_float2(v.x, v.y));
    __nv_bfloat162 h1 = __float22bfloat162_rn(make_float2(v.z, v.w));
    float2 f0 = __bfloat1622float2(h0);
    float2 f1 = __bfloat1622float2(h1);
    __nv_bfloat162 l0 = __float22bfloat162_rn(make_float2(v.x - f0.x, v.y - f0.y));
    __nv_bfloat162 l1 = __float22bfloat162_rn(make_float2(v.z - f1.x, v.w - f1.y));
    hi.x = *(uint32_t*)&h0; hi.y = *(uint32_t*)&h1;
    lo.x = *(uint32_t*)&l0; lo.y = *(uint32_t*)&l1;
}

__device__ __forceinline__ void pack_hl(float a, float b, uint32_t& hi, uint32_t& lo) {
    __nv_bfloat162 h = __float22bfloat162_rn(make_float2(a, b));
    float2 f = __bfloat1622float2(h);
    __nv_bfloat162 l = __float22bfloat162_rn(make_float2(a - f.x, b - f.y));
    hi = *(uint32_t*)&h;
    lo = *(uint32_t*)&l;
}

// ===================== batched input split =================================
__global__ __launch_bounds__(256) void split_kernel(
    const float* __restrict__ s0, const float* __restrict__ s1,
    const float* __restrict__ s2, bf16* __restrict__ hib, bf16* __restrict__ lob)
{
    const float* src = (blockIdx.y == 0) ? s0 : (blockIdx.y == 1) ? s1 : s2;
    const size_t off = (size_t)blockIdx.y * MM * DD;
    const size_t base = ((size_t)blockIdx.x * 256 + threadIdx.x) * 8;
    float4 a = *(const float4*)&src[base];
    float4 b = *(const float4*)&src[base + 4];
    uint2 h0, l0, h1, l1;
    split4(a, h0, l0);
    split4(b, h1, l1);
    uint4 hv; hv.x = h0.x; hv.y = h0.y; hv.z = h1.x; hv.w = h1.y;
    uint4 lv; lv.x = l0.x; lv.y = l0.y; lv.z = l1.x; lv.w = l1.y;
    *(uint4*)&hib[off + base] = hv;
    *(uint4*)&lob[off + base] = lv;
}

// ===================== batched weight transpose + split ====================
__global__ __launch_bounds__(256) void transpose_split_kernel(
    const float* __restrict__ w0, const float* __restrict__ w1,
    const float* __restrict__ w2, const float* __restrict__ w3,
    bf16* __restrict__ dhib, bf16* __restrict__ dlob)
{
    const float* src = (blockIdx.z == 0) ? w0 : (blockIdx.z == 1) ? w1
                     : (blockIdx.z == 2) ? w2 : w3;
    bf16* dhi = dhib + (size_t)blockIdx.z * DD * DD;
    bf16* dlo = dlob + (size_t)blockIdx.z * DD * DD;
    __shared__ float t[32][33];
    const int tid = threadIdx.x;
    const int x = blockIdx.x * 32 + (tid & 31);
    const int y0 = blockIdx.y * 32 + (tid >> 5);
#pragma unroll
    for (int r = 0; r < 4; r++)
        t[(tid >> 5) + r * 8][tid & 31] = src[(size_t)(y0 + r * 8) * DD + x];
    __syncthreads();
    const int x2 = blockIdx.y * 32 + (tid & 31);
    const int y2 = blockIdx.x * 32 + (tid >> 5);
#pragma unroll
    for (int r = 0; r < 4; r++) {
        const float v = t[tid & 31][(tid >> 5) + r * 8];
        const bf16 h = __float2bfloat16(v);
        const bf16 l = __float2bfloat16(v - __bfloat162float(h));
        dhi[(size_t)(y2 + r * 8) * DD + x2] = h;
        dlo[(size_t)(y2 + r * 8) * DD + x2] = l;
    }
}

// ===================== bf16x3 GEMM, pass-major MMA order ===================
#define GA_HI 0
#define GA_LO 10240
#define GB_HI 20480
#define GB_LO 40960
#define STAGE_B 61440
#define GEMM_SMEM3 (3 * STAGE_B)

template <int MODE>
__global__ __launch_bounds__(512, 1) void gemm_bf16_kernel(
    const bf16* __restrict__ Ahi, const bf16* __restrict__ Alo,
    const bf16* __restrict__ Bhi, const bf16* __restrict__ Blo,
    const float* __restrict__ bias, float* __restrict__ C,
    bf16* __restrict__ Chi, bf16* __restrict__ Clo)
{
    extern __shared__ char smem[];
    const uint32_t sb = smem_u32(smem);
    const int tid  = threadIdx.x;
    const int wid  = tid >> 5;
    const int lane = tid & 31;
    const int wm   = wid & 1;
    const int wn   = wid >> 1;
    const int m0 = blockIdx.y * 128;
    const int n0 = blockIdx.x * 256;

    float acc[4][4][4];
#pragma unroll
    for (int i = 0; i < 4; i++)
#pragma unroll
        for (int j = 0; j < 4; j++)
#pragma unroll
            for (int q = 0; q < 4; q++) acc[i][j][q] = 0.f;

    auto issue = [&](int c) {
        if (c < 32) {
            const uint32_t st = sb + (c % 3) * STAGE_B;
            const int k0 = c * 32;
            {
                const int row = tid >> 2, g = tid & 3;
                const size_t ga = (size_t)(m0 + row) * DD + k0 + g * 8;
                const uint32_t so = (uint32_t)(row * 80 + g * 16);
                CP16(st + GA_HI + so, Ahi + ga);
                CP16(st + GA_LO + so, Alo + ga);
            }
#pragma unroll
            for (int r = 0; r < 2; r++) {
                const int idx = tid + r * 512;
                const int row = idx >> 2, g = idx & 3;
                const size_t gb = (size_t)(n0 + row) * DD + k0 + g * 8;
                const uint32_t so = (uint32_t)(row * 80 + g * 16);
                CP16(st + GB_HI + so, Bhi + gb);
                CP16(st + GB_LO + so, Blo + gb);
            }
        }
        CP_COMMIT();
    };

    issue(0);
    issue(1);

    const uint32_t a_off = (uint32_t)((wm * 64 + (lane & 15)) * 80 + (lane >> 4) * 16);
    const uint32_t b_off = (uint32_t)((wn * 32 + (lane & 15)) * 80 + (lane >> 4) * 16);

    for (int c = 0; c < 32; c++) {
        CP_WAIT1();
        __syncthreads();
        issue(c + 2);

        const uint32_t bb = sb + (c % 3) * STAGE_B;
#pragma unroll
        for (int ks = 0; ks < 2; ks++) {
            uint32_t ah[4][4], al[4][4], bh[2][4], bl[2][4];
#pragma unroll
            for (int mt = 0; mt < 4; mt++) {
                const uint32_t ad = bb + a_off + (uint32_t)(mt * 16 * 80 + ks * 32);
                LDSM4(ah[mt][0], ah[mt][1], ah[mt][2], ah[mt][3], ad + GA_HI);
                LDSM4(al[mt][0], al[mt][1], al[mt][2], al[mt][3], ad + GA_LO);
            }
#pragma unroll
            for (int p = 0; p < 2; p++) {
                const uint32_t bd = bb + b_off + (uint32_t)(p * 16 * 80 + ks * 32);
                LDSM4(bh[p][0], bh[p][1], bh[p][2], bh[p][3], bd + GB_HI);
                LDSM4(bl[p][0], bl[p][1], bl[p][2], bl[p][3], bd + GB_LO);
            }
            // pass-major: 16 independent accumulators between dependent reuses
#pragma unroll
            for (int pass = 0; pass < 3; pass++) {
#pragma unroll
                for (int mt = 0; mt < 4; mt++) {
#pragma unroll
                    for (int nt = 0; nt < 4; nt++) {
                        const int p = nt >> 1, q2 = nt & 1;
                        if (pass == 0) {
                            MMA16816(acc[mt][nt], ah[mt][0], ah[mt][1], ah[mt][2], ah[mt][3],
                                     bh[p][q2], bh[p][q2 + 2]);
                        } else if (pass == 1) {
                            MMA16816(acc[mt][nt], ah[mt][0], ah[mt][1], ah[mt][2], ah[mt][3],
                                     bl[p][q2], bl[p][q2 + 2]);
                        } else {
                            MMA16816(acc[mt][nt], al[mt][0], al[mt][1], al[mt][2], al[mt][3],
                                     bh[p][q2], bh[p][q2 + 2]);
                        }
                    }
                }
            }
        }
    }

#pragma unroll
    for (int nt = 0; nt < 4; nt++) {
        const int col = n0 + wn * 32 + nt * 8 + (lane & 3) * 2;
        const float2 bv = *(const float2*)&bias[col];
#pragma unroll
        for (int mt = 0; mt < 4; mt++) {
            const int r0 = m0 + wm * 64 + mt * 16 + (lane >> 2);
#pragma unroll
            for (int half = 0; half < 2; half++) {
                const int row = r0 + half * 8;
                float2 v;
                v.x = acc[mt][nt][half * 2 + 0] + bv.x;
                v.y = acc[mt][nt][half * 2 + 1] + bv.y;
                if (MODE == 1) {
                    const int b = row >> 10, sdx = row & (SS - 1);
                    const int h = col >> 6, d = col & (HDD - 1);
                    const size_t idx = (((size_t)(b * HH + h) * SS) + sdx) * HDD + d;
                    __nv_bfloat162 hv, lv;
                    hv.x = __float2bfloat16(v.x);
                    hv.y = __float2bfloat16(v.y);
                    lv.x = __float2bfloat16(v.x - __bfloat162float(hv.x));
                    lv.y = __float2bfloat16(v.y - __bfloat162float(hv.y));
                    *(__nv_bfloat162*)&Chi[idx] = hv;
                    *(__nv_bfloat162*)&Clo[idx] = lv;
                } else {
                    *(float2*)&C[(size_t)row * DD + col] = v;
                }
            }
        }
    }
}

// ======== attention: register-P FA2, pass-major MMA order ==================
#define AT_QHI 0
#define AT_QLO 18432
#define AT_KV0 36864
#define AT_KVSZ 73728
#define AT_KHI 0
#define AT_KLO 18432
#define AT_VHI 36864
#define AT_VLO 55296
#define ATTN3_SMEM (AT_KV0 + 2 * AT_KVSZ)

__global__ __launch_bounds__(256, 1) void attn_mma_kernel(
    const bf16* __restrict__ Qhi_g, const bf16* __restrict__ Qlo_g,
    const bf16* __restrict__ Khi_g, const bf16* __restrict__ Klo_g,
    const bf16* __restrict__ Vhi_g, const bf16* __restrict__ Vlo_g,
    float* __restrict__ wout, float* __restrict__ rowinv_g,
    bf16* __restrict__ ctxhi, bf16* __restrict__ ctxlo)
{
    extern __shared__ char sm[];
    const uint32_t sb = smem_u32(sm);
    const int tid  = threadIdx.x;
    const int lane = tid & 31;
    const int wid  = tid >> 5;
    const int r0   = wid * 16;
    const int bh   = blockIdx.y;
    const int qt   = gridDim.x - 1 - blockIdx.x;
    const int q0   = qt * 128;
    const int b    = bh >> 4, h = bh & 15;
    const int nkt  = qt + 1;

    {
        const size_t base = ((size_t)bh * SS + q0) * HDD;
#pragma unroll
        for (int i = 0; i < 4; i++) {
            const int e = tid + i * 256;
            const int r = e >> 3, c8 = (e & 7) * 8;
            const uint32_t so = (uint32_t)(r * 144 + c8 * 2);
            *(uint4*)(sm + AT_QHI + so) = *(const uint4*)&Qhi_g[base + r * 64 + c8];
            *(uint4*)(sm + AT_QLO + so) = *(const uint4*)&Qlo_g[base + r * 64 + c8];
        }
    }

    auto issue = [&](int kt) {
        if (kt < nkt) {
            const uint32_t kvb = sb + AT_KV0 + (kt & 1) * AT_KVSZ;
            const size_t gbase = ((size_t)bh * SS + kt * 128) * HDD;
#pragma unroll
            for (int i = 0; i < 4; i++) {
                const int e = tid + i * 256;
                const int r = e >> 3, g = e & 7;
                const uint32_t off = (uint32_t)(r * 144 + g * 16);
                const size_t go = gbase + r * 64 + g * 8;
                CP16(kvb + AT_KHI + off, Khi_g + go);
                CP16(kvb + AT_KLO + off, Klo_g + go);
                CP16(kvb + AT_VHI + off, Vhi_g + go);
                CP16(kvb + AT_VLO + off, Vlo_g + go);
            }
        }
        CP_COMMIT();
    };
    issue(0);

    float pv[8][4];
#pragma unroll
    for (int i = 0; i < 8; i++)
#pragma unroll
        for (int j = 0; j < 4; j++) pv[i][j] = 0.f;
    float ps0 = 0.f, ps1 = 0.f;

    const int grow0 = q0 + r0 + (lane >> 2);
    const int grow1 = grow0 + 8;
    const uint32_t qa = sb + AT_QHI + (uint32_t)((r0 + (lane & 15)) * 144 + (lane >> 4) * 16);

    for (int kt = 0; kt < nkt; kt++) {
        __syncthreads();
        issue(kt + 1);
        CP_WAIT1();
        __syncthreads();
        const uint32_t kvb = sb + AT_KV0 + (kt & 1) * AT_KVSZ;

        // ---- scores ----
        float accE[16][4];
#pragma unroll
        for (int i = 0; i < 16; i++)
#pragma unroll
            for (int j = 0; j < 4; j++) accE[i][j] = 0.f;

#pragma unroll
        for (int ks = 0; ks < 4; ks++) {
            uint32_t ah[4], al[4];
            LDSM4(ah[0], ah[1], ah[2], ah[3], qa + ks * 32);
            LDSM4(al[0], al[1], al[2], al[3], qa + (AT_QLO - AT_QHI) + ks * 32);
            // load K fragments for two n-blocks at a time, pass-major inside
#pragma unroll
            for (int nb2 = 0; nb2 < 4; nb2++) {
                uint32_t kh4[2][4], kl4[2][4];
#pragma unroll
                for (int u = 0; u < 2; u++) {
                    const int nb = nb2 * 2 + u;
                    const uint32_t ka = kvb + AT_KHI +
                        (uint32_t)((nb * 16 + (lane & 15)) * 144 + ks * 32 + (lane >> 4) * 16);
                    LDSM4(kh4[u][0], kh4[u][1], kh4[u][2], kh4[u][3], ka);
                    LDSM4(kl4[u][0], kl4[u][1], kl4[u][2], kl4[u][3], ka + (AT_KLO - AT_KHI));
                }
#pragma unroll
                for (int pass = 0; pass < 3; pass++)
#pragma unroll
                    for (int u = 0; u < 2; u++)
#pragma unroll
                        for (int hh = 0; hh < 2; hh++) {
                            float* c = accE[(nb2 * 2 + u) * 2 + hh];
                            if (pass == 0)
                                MMA16816(c, ah[0], ah[1], ah[2], ah[3],
                                         kh4[u][hh], kh4[u][hh + 2]);
                            else if (pass == 1)
                                MMA16816(c, ah[0], ah[1], ah[2], ah[3],
                                         kl4[u][hh], kl4[u][hh + 2]);
                            else
                                MMA16816(c, al[0], al[1], al[2], al[3],
                                         kh4[u][hh], kh4[u][hh + 2]);
                        }
            }
        }

        // ---- exp + mask + unnormalized W write + rowsum ----
#pragma unroll
        for (int nt = 0; nt < 16; nt++) {
            const int gc = kt * 128 + nt * 8 + (lane & 3) * 2;
            float e00 = (gc     <= grow0) ? __expf(accE[nt][0] * 0.125f) : 0.f;
            float e01 = (gc + 1 <= grow0) ? __expf(accE[nt][1] * 0.125f) : 0.f;
            float e10 = (gc     <= grow1) ? __expf(accE[nt][2] * 0.125f) : 0.f;
            float e11 = (gc + 1 <= grow1) ? __expf(accE[nt][3] * 0.125f) : 0.f;
            accE[nt][0] = e00; accE[nt][1] = e01;
            accE[nt][2] = e10; accE[nt][3] = e11;
            ps0 += e00 + e01;
            ps1 += e10 + e11;
            float2 w0; w0.x = e00; w0.y = e01;
            float2 w1; w1.x = e10; w1.y = e11;
            __stcs((float2*)&wout[((size_t)bh * SS + grow0) * SS + gc], w0);
            __stcs((float2*)&wout[((size_t)bh * SS + grow1) * SS + gc], w1);
        }

        // ---- PV (pass-major across nd, hh) ----
#pragma unroll
        for (int j = 0; j < 8; j++) {
            uint32_t ph[4], pl[4];
            pack_hl(accE[2 * j][0],     accE[2 * j][1],     ph[0], pl[0]);
            pack_hl(accE[2 * j][2],     accE[2 * j][3],     ph[1], pl[1]);
            pack_hl(accE[2 * j + 1][0], accE[2 * j + 1][1], ph[2], pl[2]);
            pack_hl(accE[2 * j + 1][2], accE[2 * j + 1][3], ph[3], pl[3]);
            uint32_t vh4[4][4], vl4[4][4];
#pragma unroll
            for (int nd = 0; nd < 4; nd++) {
                const uint32_t va = kvb + AT_VHI + (uint32_t)(
                    (j * 16 + ((lane >> 4) & 1) * 8 + (lane & 7)) * 144
                    + (nd * 16 + ((lane >> 3) & 1) * 8) * 2);
                LDSM4T(vh4[nd][0], vh4[nd][1], vh4[nd][2], vh4[nd][3], va);
                LDSM4T(vl4[nd][0], vl4[nd][1], vl4[nd][2], vl4[nd][3], va + (AT_VLO - AT_VHI));
            }
#pragma unroll
            for (int pass = 0; pass < 3; pass++)
#pragma unroll
                for (int nd = 0; nd < 4; nd++)
#pragma unroll
                    for (int hh = 0; hh < 2; hh++) {
                        float* c = pv[nd * 2 + hh];
                        if (pass == 0)
                            MMA16816(c, ph[0], ph[1], ph[2], ph[3],
                                     vh4[nd][hh], vh4[nd][hh + 2]);
                        else if (pass == 1)
                            MMA16816(c, ph[0], ph[1], ph[2], ph[3],
                                     vl4[nd][hh], vl4[nd][hh + 2]);
                        else
                            MMA16816(c, pl[0], pl[1], pl[2], pl[3],
                                     vh4[nd][hh], vh4[nd][hh + 2]);
                    }
        }
    }

    ps0 += __shfl_xor_sync(~0u, ps0, 1);
    ps0 += __shfl_xor_sync(~0u, ps0, 2);
    ps1 += __shfl_xor_sync(~0u, ps1, 1);
    ps1 += __shfl_xor_sync(~0u, ps1, 2);
    const float inv0 = 1.0f / ps0;
    const float inv1 = 1.0f / ps1;
    if ((lane & 3) == 0) {
        rowinv_g[(size_t)bh * SS + grow0] = inv0;
        rowinv_g[(size_t)bh * SS + grow1] = inv1;
    }

#pragma unroll
    for (int dt = 0; dt < 8; dt++) {
        const int d = h * 64 + dt * 8 + (lane & 3) * 2;
        const float o0x = pv[dt][0] * inv0, o0y = pv[dt][1] * inv0;
        const float o1x = pv[dt][2] * inv1, o1y = pv[dt][3] * inv1;
        __nv_bfloat162 hv, lv;
        hv.x = __float2bfloat16(o0x); hv.y = __float2bfloat16(o0y);
        lv.x = __float2bfloat16(o0x - __bfloat162float(hv.x));
        lv.y = __float2bfloat16(o0y - __bfloat162float(hv.y));
        size_t idx = ((size_t)(b * SS + grow0)) * DD + d;
        *(__nv_bfloat162*)&ctxhi[idx] = hv;
        *(__nv_bfloat162*)&ctxlo[idx] = lv;
        hv.x = __float2bfloat16(o1x); hv.y = __float2bfloat16(o1y);
        lv.x = __float2bfloat16(o1x - __bfloat162float(hv.x));
        lv.y = __float2bfloat16(o1y - __bfloat162float(hv.y));
        idx = ((size_t)(b * SS + grow1)) * DD + d;
        *(__nv_bfloat162*)&ctxhi[idx] = hv;
        *(__nv_bfloat162*)&ctxlo[idx] = lv;
    }
}

// ============================ normalize weights ============================
__global__ __launch_bounds__(128) void norm_kernel(
    float* __restrict__ w, const float* __restrict__ rowinv)
{
    const int row = blockIdx.x;
    const int q = row & (SS - 1);
    const float inv = rowinv[row];
    float4* wr = (float4*)(w + (size_t)row * SS);
    const int tid = threadIdx.x;
#pragma unroll
    for (int i = 0; i < 2; i++) {
        const int j = tid + i * 128;
        const int k = j * 4;
        float4 v;
        if (k + 3 <= q) {
            v = wr[j];
            v.x *= inv; v.y *= inv; v.z *= inv; v.w *= inv;
        } else if (k > q) {
            v.x = v.y = v.z = v.w = 0.f;
        } else {
            v = wr[j];
            v.x = (k     <= q) ? v.x * inv : 0.f;
            v.y = (k + 1 <= q) ? v.y * inv : 0.f;
            v.z = (k + 2 <= q) ? v.z * inv : 0.f;
            v.w = (k + 3 <= q) ? v.w * inv : 0.f;
        }
        wr[j] = v;
    }
}

// ============================ launch =======================================
extern "C" void kernel_launch(void* const* d_in, const int* in_sizes, int n_in,
                              void* d_out, int out_size)
{
    const float* q  = (const float*)d_in[0];
    const float* k  = (const float*)d_in[1];
    const float* v  = (const float*)d_in[2];
    const float* Wq = (const float*)d_in[4];
    const float* bq = (const float*)d_in[5];
    const float* Wk = (const float*)d_in[6];
    const float* bk = (const float*)d_in[7];
    const float* Wv = (const float*)d_in[8];
    const float* bv = (const float*)d_in[9];
    const float* Wo = (const float*)d_in[10];
    const float* bo = (const float*)d_in[11];

    float* out = (float*)d_out;

    float *wscr, *rowinv;
    bf16 *Qhi, *Qlo, *Khi, *Klo, *Vhi, *Vlo, *inhi, *inlo, *WThi, *WTlo, *ctxhi, *ctxlo;
    cudaGetSymbolAddress((void**)&wscr,   g_wscratch);
    cudaGetSymbolAddress((void**)&rowinv, g_rowinv);
    cudaGetSymbolAddress((void**)&Qhi,    g_Qhi);
    cudaGetSymbolAddress((void**)&Qlo,    g_Qlo);
    cudaGetSymbolAddress((void**)&Khi,    g_Khi);
    cudaGetSymbolAddress((void**)&Klo,    g_Klo);
    cudaGetSymbolAddress((void**)&Vhi,    g_Vhi);
    cudaGetSymbolAddress((void**)&Vlo,    g_Vlo);
    cudaGetSymbolAddress((void**)&inhi,   g_inhi);
    cudaGetSymbolAddress((void**)&inlo,   g_inlo);
    cudaGetSymbolAddress((void**)&WThi,   g_WThi);
    cudaGetSymbolAddress((void**)&WTlo,   g_WTlo);
    cudaGetSymbolAddress((void**)&ctxhi,  g_ctxhi);
    cudaGetSymbolAddress((void**)&ctxlo,  g_ctxlo);

    const size_t MD = (size_t)MM * DD;
    const size_t D2 = (size_t)DD * DD;

    float* wout = ((size_t)out_size >= OUT_ELEMS + W_ELEMS) ? (out + OUT_ELEMS) : wscr;

    cudaFuncSetAttribute(gemm_bf16_kernel<0>,
                         cudaFuncAttributeMaxDynamicSharedMemorySize, GEMM_SMEM3);
    cudaFuncSetAttribute(gemm_bf16_kernel<1>,
                         cudaFuncAttributeMaxDynamicSharedMemorySize, GEMM_SMEM3);
    cudaFuncSetAttribute(attn_mma_kernel,
                         cudaFuncAttributeMaxDynamicSharedMemorySize, ATTN3_SMEM);

    split_kernel<<<dim3(MD / (256 * 8), 3), 256>>>(q, k, v, inhi, inlo);
    transpose_split_kernel<<<dim3(32, 32, 4), 256>>>(Wq, Wk, Wv, Wo, WThi, WTlo);

    const dim3 ggemm(DD / 256, MM / 128);
    gemm_bf16_kernel<1><<<ggemm, 512, GEMM_SMEM3>>>(
        inhi + 0 * MD, inlo + 0 * MD, WThi + 0 * D2, WTlo + 0 * D2, bq, nullptr, Qhi, Qlo);
    gemm_bf16_kernel<1><<<ggemm, 512, GEMM_SMEM3>>>(
        inhi + 1 * MD, inlo + 1 * MD, WThi + 1 * D2, WTlo + 1 * D2, bk, nullptr, Khi, Klo);
    gemm_bf16_kernel<1><<<ggemm, 512, GEMM_SMEM3>>>(
        inhi + 2 * MD, inlo + 2 * MD, WThi + 2 * D2, WTlo + 2 * D2, bv, nullptr, Vhi, Vlo);

    attn_mma_kernel<<<dim3(SS / 128, BHT), 256, ATTN3_SMEM>>>(
        Qhi, Qlo, Khi, Klo, Vhi, Vlo, wout, rowinv, ctxhi, ctxlo);

    norm_kernel<<<BHT * SS, 128>>>(wout, rowinv);

    gemm_bf16_kernel<0><<<ggemm, 512, GEMM_SMEM3>>>(
        ctxhi, ctxlo, WThi + 3 * D2, WTlo + 3 * D2, bo, out, nullptr, nullptr);
}